// round 6
// baseline (speedup 1.0000x reference)
#include <cuda_runtime.h>
#include <cstdint>

#define MAXB 2048
#define ISTR 260   // input smem batch stride (65 16B-units, odd -> conflict-free)

__device__ float g_qW[MAXB * 1024];   // (q_h @ W_k,h)/TEMP  [b][h][j]
__device__ float g_ctx[MAXB * 1024];  // attn @ seq          [b][h][j]

extern __shared__ float s_dyn[];

// ---------------- f32x2 / cp.async helpers ----------------
__device__ __forceinline__ uint64_t pk(float x, float y){
    uint64_t r; asm("mov.b64 %0, {%1,%2};" : "=l"(r) : "f"(x), "f"(y)); return r;
}
__device__ __forceinline__ float lo32(uint64_t v){ return __uint_as_float((unsigned)(v & 0xffffffffu)); }
__device__ __forceinline__ float hi32(uint64_t v){ return __uint_as_float((unsigned)(v >> 32)); }
__device__ __forceinline__ float hadd(uint64_t v){ return lo32(v) + hi32(v); }
__device__ __forceinline__ void fma2(uint64_t& d, uint64_t a, uint64_t b){
    asm("fma.rn.f32x2 %0, %1, %2, %0;" : "+l"(d) : "l"(a), "l"(b));
}
__device__ __forceinline__ void mul2(uint64_t& d, uint64_t r){
    asm("mul.rn.f32x2 %0, %1, %2;" : "=l"(d) : "l"(d), "l"(r));
}
__device__ __forceinline__ void ldsv2(uint64_t& a, uint64_t& b, const float* p){
    uint32_t sp = (uint32_t)__cvta_generic_to_shared(p);
    asm volatile("ld.shared.v2.u64 {%0,%1}, [%2];" : "=l"(a), "=l"(b) : "r"(sp));
}
__device__ __forceinline__ void cp16(float* dst, const float* src){
    uint32_t s = (uint32_t)__cvta_generic_to_shared(dst);
    asm volatile("cp.async.cg.shared.global [%0], [%1], 16;" :: "r"(s), "l"(src));
}
#define CP_COMMIT() asm volatile("cp.async.commit_group;" ::: "memory")
#define CP_WAIT(N)  asm volatile("cp.async.wait_group %0;" :: "n"(N) : "memory")

// ---------------------------------------------------------------------------
// Slab GEMV core: out[16 b x 256 c] += in[16 x K] @ W[256 x K]^T.
// Thread map: bg = t&3 (batches i*4+bg), cg = t>>2 (cols cg*4..+3).
// Warp = 8 cgs x 4 bgs -> weight LDS.128 is 8 distinct units x 4-way bcast
// (1 phase, swizzle keeps bank groups distinct), input LDS.128 is 4 distinct
// units x 8-way bcast (1 phase via odd-unit ISTR stride + i*4+bg batching).
// Weight slab = 32k x 256c (32KB), swizzled 16B units, cp.async dbl-buffer.
// ---------------------------------------------------------------------------
__device__ __forceinline__ void gemv_issue(float* wbuf, const float* __restrict__ wg,
                                           int wstride, int j, int t){
    float* dst = wbuf + (j & 1) * 8192;
    const float* src = wg + j * 32;
    #pragma unroll
    for (int p = 0; p < 8; p++){
        int u = p*256 + t;                 // 16B unit: row c = u>>3, half h = u&7
        int c = u >> 3, h = u & 7;
        int su = u ^ ((u >> 5) & 7);       // swizzle
        cp16(dst + su*4, src + (size_t)c*wstride + h*4);
    }
    CP_COMMIT();
}

__device__ __forceinline__ void gemv_slabs(const float* __restrict__ wg, int wstride,
                                           int nslab,
                                           const float* __restrict__ inp,
                                           float* wbuf, uint64_t (&acc)[4][4], int t){
    int bg = t & 3, cg = t >> 2;
    int c0 = cg * 4;
    int swm = cg & 7;
    gemv_issue(wbuf, wg, wstride, 0, t);
    if (nslab > 1) gemv_issue(wbuf, wg, wstride, 1, t);
    const float* ib0 = inp + (0*4 + bg)*ISTR;
    const float* ib1 = inp + (1*4 + bg)*ISTR;
    const float* ib2 = inp + (2*4 + bg)*ISTR;
    const float* ib3 = inp + (3*4 + bg)*ISTR;
    for (int j = 0; j < nslab; j++){
        if (j + 1 < nslab) CP_WAIT(1); else CP_WAIT(0);
        __syncthreads();
        const float* wcur = wbuf + (j & 1) * 8192;
        const float* wc0 = wcur + (c0+0)*32;
        const float* wc1 = wcur + (c0+1)*32;
        const float* wc2 = wcur + (c0+2)*32;
        const float* wc3 = wcur + (c0+3)*32;
        int kb = j * 32;
        #pragma unroll
        for (int u8 = 0; u8 < 8; u8++){
            int wof = (u8 ^ swm) * 4;
            uint64_t w[4][2];
            ldsv2(w[0][0], w[0][1], wc0 + wof);
            ldsv2(w[1][0], w[1][1], wc1 + wof);
            ldsv2(w[2][0], w[2][1], wc2 + wof);
            ldsv2(w[3][0], w[3][1], wc3 + wof);
            uint64_t iv[4][2];
            ldsv2(iv[0][0], iv[0][1], ib0 + kb + u8*4);
            ldsv2(iv[1][0], iv[1][1], ib1 + kb + u8*4);
            ldsv2(iv[2][0], iv[2][1], ib2 + kb + u8*4);
            ldsv2(iv[3][0], iv[3][1], ib3 + kb + u8*4);
            #pragma unroll
            for (int c4 = 0; c4 < 4; c4++)
                #pragma unroll
                for (int b = 0; b < 4; b++){
                    fma2(acc[c4][b], w[c4][0], iv[b][0]);
                    fma2(acc[c4][b], w[c4][1], iv[b][1]);
                }
        }
        __syncthreads();
        if (j + 2 < nslab) gemv_issue(wbuf, wg, wstride, j+2, t);
    }
}

#define ZACC(acc) { _Pragma("unroll") for (int _c=0;_c<4;_c++) _Pragma("unroll") for (int _b=0;_b<4;_b++) acc[_c][_b]=0; }

// ---------------------------------------------------------------------------
// K1: q = src @ w_qs^T ; qW[h] = (q_h @ W_k,h) * 0.125
// ---------------------------------------------------------------------------
__global__ void __launch_bounds__(256) k1_qw(const float* __restrict__ src,
                                             const float* __restrict__ w_qs,
                                             const float* __restrict__ w_ks,
                                             int B)
{
    float* src_s = s_dyn;            // 16*260 = 4160
    float* q_s   = s_dyn + 4160;     // 4160
    float* wbuf  = s_dyn + 8320;     // 16384
    int t  = threadIdx.x;
    int b0 = blockIdx.x * 16;
    int bg = t & 3, cg = t >> 2;
    int c0 = cg * 4;

    #pragma unroll
    for (int p = 0; p < 4; p++){
        int u = p*256 + t;
        int b = u >> 6, k4 = u & 63;
        cp16(src_s + b*ISTR + k4*4, src + (size_t)b0*256 + u*4);
    }
    CP_COMMIT();

    uint64_t acc[4][4];
    ZACC(acc);
    gemv_slabs(w_qs, 256, 8, src_s, wbuf, acc, t);
    #pragma unroll
    for (int i = 0; i < 4; i++){
        float4 v = make_float4(hadd(acc[0][i]), hadd(acc[1][i]),
                               hadd(acc[2][i]), hadd(acc[3][i]));
        *(float4*)(q_s + (i*4 + bg)*ISTR + c0) = v;
    }
    __syncthreads();

    // ---- head stage: coalesced LDG weights, q broadcast from smem ----
    int hcg = t & 63, hbg = t >> 6;
    int hc0 = hcg * 4;
    #pragma unroll
    for (int h = 0; h < 4; h++){
        ZACC(acc);
        const float* wbase = w_ks + (size_t)(h*64)*256 + hc0;
        #pragma unroll 4
        for (int d = 0; d < 64; d += 2){
            float4 wa = __ldg((const float4*)(wbase + (size_t)d*256));
            float4 wb = __ldg((const float4*)(wbase + (size_t)(d+1)*256));
            uint64_t w0 = pk(wa.x, wb.x), w1 = pk(wa.y, wb.y);
            uint64_t w2 = pk(wa.z, wb.z), w3 = pk(wa.w, wb.w);
            #pragma unroll
            for (int i = 0; i < 4; i++){
                uint64_t qp = *(const uint64_t*)(q_s + (i*4 + hbg)*ISTR + h*64 + d);
                fma2(acc[0][i], w0, qp);
                fma2(acc[1][i], w1, qp);
                fma2(acc[2][i], w2, qp);
                fma2(acc[3][i], w3, qp);
            }
        }
        #pragma unroll
        for (int i = 0; i < 4; i++){
            float4 v = make_float4(hadd(acc[0][i])*0.125f, hadd(acc[1][i])*0.125f,
                                   hadd(acc[2][i])*0.125f, hadd(acc[3][i])*0.125f);
            *(float4*)(g_qW + (size_t)(b0 + i*4 + hbg)*1024 + h*256 + hc0) = v;
        }
    }
}

// ---------------------------------------------------------------------------
// K2: flash-style attention, qW operand register-resident.
// ---------------------------------------------------------------------------
__device__ __forceinline__ void k2_issue(float* dst, const float* gsrc, int t){
    #pragma unroll
    for (int j = 0; j < 8; j++){
        int seg = j*256 + t;
        cp16(dst + seg*4, gsrc + seg*4);
    }
    CP_COMMIT();
}

__global__ void __launch_bounds__(256, 3) k2_attn(const float* __restrict__ seq,
                                                  const void* __restrict__ mask,
                                                  int B,
                                                  float* __restrict__ attn_out)
{
    float* chk0 = s_dyn;            // 8192
    float* chk1 = s_dyn + 8192;     // 8192
    float* sc_s = s_dyn + 16384;    // 512
    float* e_s  = s_dyn + 16896;    // 128 [n][h]
    float* m_s  = s_dyn + 17024;    // 4
    float* s_s  = s_dyn + 17028;    // 4
    float* r_s  = s_dyn + 17032;    // 4 (+pad)
    __shared__ int s_u8;

    int t = threadIdx.x, b = blockIdx.x;
    int w = t >> 5, lane = t & 31;

    if (t == 0) s_u8 = 0;
    __syncthreads();
    { unsigned wv = ((const unsigned*)mask)[t]; if (wv > 1u) atomicOr(&s_u8, 1); }

    uint64_t q[4][4];
    {
        const ulonglong2* qp = (const ulonglong2*)(g_qW + (size_t)b*1024 + lane*8);
        #pragma unroll
        for (int h = 0; h < 4; h++){
            ulonglong2 v0 = qp[h*64];
            ulonglong2 v1 = qp[h*64 + 1];
            q[h][0] = v0.x; q[h][1] = v0.y; q[h][2] = v1.x; q[h][3] = v1.y;
        }
    }
    if (t < 4){ m_s[t] = -1e30f; s_s[t] = 0.f; r_s[t] = 1.f; }

    const float* gseq = seq + (size_t)b*32768;
    k2_issue(chk0, gseq, t);
    k2_issue(chk1, gseq + 8192, t);

    uint64_t c01 = 0, c23 = 0;
    int is_u8 = 0;

    #pragma unroll
    for (int c = 0; c < 4; c++){
        if (c < 3) CP_WAIT(1); else CP_WAIT(0);
        __syncthreads();
        if (c == 0) is_u8 = s_u8;
        const float* cb = (c & 1) ? chk1 : chk0;

        #pragma unroll
        for (int r = 0; r < 4; r++){
            int nl = r*8 + w;
            int ng = c*32 + nl;
            const float* vp = cb + nl*256 + lane*8;
            uint64_t v0, v1, v2, v3;
            ldsv2(v0, v1, vp);
            ldsv2(v2, v3, vp + 4);
            float sc4[4];
            #pragma unroll
            for (int h = 0; h < 4; h++){
                uint64_t a = 0;
                fma2(a, v0, q[h][0]); fma2(a, v1, q[h][1]);
                fma2(a, v2, q[h][2]); fma2(a, v3, q[h][3]);
                sc4[h] = hadd(a);
            }
            #pragma unroll
            for (int o = 16; o > 0; o >>= 1){
                #pragma unroll
                for (int h = 0; h < 4; h++)
                    sc4[h] += __shfl_xor_sync(0xffffffffu, sc4[h], o);
            }
            if (lane < 4){
                int h = lane;
                int mrow = (4*b + h) % B;
                int mv = is_u8 ? (int)((const unsigned char*)mask)[(size_t)mrow*128 + ng]
                               : ((const int*)mask)[(size_t)mrow*128 + ng];
                sc_s[h*128 + ng] = mv ? -1e10f : sc4[h];
            }
        }
        __syncthreads();

        if (w < 4){
            int h = w;
            float s = sc_s[h*128 + c*32 + lane];
            float m = s;
            #pragma unroll
            for (int o = 16; o > 0; o >>= 1) m = fmaxf(m, __shfl_xor_sync(0xffffffffu, m, o));
            float Mold = m_s[h];
            float Mnew = fmaxf(Mold, m);
            float e = expf(s - Mnew);
            float ss = e;
            #pragma unroll
            for (int o = 16; o > 0; o >>= 1) ss += __shfl_xor_sync(0xffffffffu, ss, o);
            e_s[lane*4 + h] = e;
            if (lane == 0){
                float rr = expf(Mold - Mnew);
                m_s[h] = Mnew;
                s_s[h] = s_s[h]*rr + ss;
                r_s[h] = rr;
            }
        }
        __syncthreads();

        {
            uint64_t r01 = *(const uint64_t*)(r_s);
            uint64_t r23 = *(const uint64_t*)(r_s + 2);
            mul2(c01, r01);
            mul2(c23, r23);
            #pragma unroll 8
            for (int n = 0; n < 32; n++){
                float sv = cb[n*256 + t];
                uint64_t svv = pk(sv, sv);
                uint64_t e01 = *(const uint64_t*)(e_s + n*4);
                uint64_t e23 = *(const uint64_t*)(e_s + n*4 + 2);
                fma2(c01, svv, e01);
                fma2(c23, svv, e23);
            }
        }
        __syncthreads();
        if (c < 2) k2_issue((c & 1) ? chk1 : chk0, gseq + (size_t)(c+2)*8192, t);
    }

    float i0 = 1.f/s_s[0], i1 = 1.f/s_s[1], i2 = 1.f/s_s[2], i3 = 1.f/s_s[3];
    float* cbg = g_ctx + (size_t)b*1024;
    cbg[t]        = lo32(c01) * i0;
    cbg[256 + t]  = hi32(c01) * i1;
    cbg[512 + t]  = lo32(c23) * i2;
    cbg[768 + t]  = hi32(c23) * i3;

    if (attn_out){
        float invs[4] = {i0, i1, i2, i3};
        #pragma unroll
        for (int k = 0; k < 2; k++){
            int idx = k*256 + t;
            int h = idx >> 7;
            attn_out[(size_t)b*512 + idx] = expf(sc_s[idx] - m_s[h]) * invs[h];
        }
    }
}

// ---------------------------------------------------------------------------
// K3: out-proj (W_v) -> fc (+bias +residual) -> LN -> fc1(concat)+relu -> fc2
// ctx staged [h][16 b][ISTR]; all row buffers stride ISTR.
// ---------------------------------------------------------------------------
#define CTXH (16*ISTR)   // 4160 floats per head block
__global__ void __launch_bounds__(256) k3_tail(const float* __restrict__ src,
        const float* __restrict__ w_vs,
        const float* __restrict__ fc_w,  const float* __restrict__ fc_b,
        const float* __restrict__ ln_g,  const float* __restrict__ ln_b,
        const float* __restrict__ fc1_w, const float* __restrict__ fc1_b,
        const float* __restrict__ fc2_w, const float* __restrict__ fc2_b,
        float* __restrict__ out)
{
    float* ctx_s = s_dyn;                 // 4*CTXH = 16640
    float* src_s = s_dyn + 16640;         // 4160
    float* o_s   = s_dyn + 20800;         // 4160
    float* x_s   = s_dyn + 24960;         // 4160
    float* h1_s  = s_dyn + 29120;         // 4160
    float* wbuf  = s_dyn + 33280;         // 16384
    float* mu_s  = s_dyn + 49664;         // 16
    float* rs_s  = s_dyn + 49680;         // 16
    int t  = threadIdx.x;
    int b0 = blockIdx.x * 16;
    int bg = t & 3, cg = t >> 2;
    int c0 = cg * 4;

    #pragma unroll
    for (int p = 0; p < 16; p++){
        int u = p*256 + t;
        int b = u >> 8, rem = u & 255, h = rem >> 6, k4 = rem & 63;
        cp16(ctx_s + h*CTXH + b*ISTR + k4*4, g_ctx + (size_t)b0*1024 + u*4);
    }
    #pragma unroll
    for (int p = 0; p < 4; p++){
        int u = p*256 + t;
        int b = u >> 6, k4 = u & 63;
        cp16(src_s + b*ISTR + k4*4, src + (size_t)b0*256 + u*4);
    }
    CP_COMMIT();

    uint64_t acc[4][4];

    // ---- out projection: col c uses ctx head c>>6 = cg>>4 ----
    ZACC(acc);
    gemv_slabs(w_vs, 256, 8, ctx_s + (cg >> 4)*CTXH, wbuf, acc, t);
    #pragma unroll
    for (int i = 0; i < 4; i++){
        float4 v = make_float4(hadd(acc[0][i]), hadd(acc[1][i]),
                               hadd(acc[2][i]), hadd(acc[3][i]));
        *(float4*)(o_s + (i*4 + bg)*ISTR + c0) = v;
    }

    // ---- fc + bias + residual ----
    ZACC(acc);
    gemv_slabs(fc_w, 256, 8, o_s, wbuf, acc, t);
    {
        float4 fb = *(const float4*)(fc_b + c0);
        #pragma unroll
        for (int i = 0; i < 4; i++){
            int bi = i*4 + bg;
            float4 sv = *(const float4*)(src_s + bi*ISTR + c0);
            float4 v = make_float4(hadd(acc[0][i]) + fb.x + sv.x,
                                   hadd(acc[1][i]) + fb.y + sv.y,
                                   hadd(acc[2][i]) + fb.z + sv.z,
                                   hadd(acc[3][i]) + fb.w + sv.w);
            *(float4*)(x_s + bi*ISTR + c0) = v;
        }
    }
    __syncthreads();

    // ---- LayerNorm (warp w handles rows 2w, 2w+1) ----
    {
        int w = t >> 5, lane = t & 31;
        #pragma unroll
        for (int rr = 0; rr < 2; rr++){
            int i = w*2 + rr;
            float s = 0.f, s2 = 0.f;
            const float4* xr = (const float4*)(x_s + i*ISTR + lane*8);
            #pragma unroll
            for (int qq = 0; qq < 2; qq++){
                float4 v = xr[qq];
                s  += v.x + v.y + v.z + v.w;
                s2 += v.x*v.x + v.y*v.y + v.z*v.z + v.w*v.w;
            }
            #pragma unroll
            for (int o = 16; o > 0; o >>= 1){
                s  += __shfl_xor_sync(0xffffffffu, s,  o);
                s2 += __shfl_xor_sync(0xffffffffu, s2, o);
            }
            if (lane == 0){
                float mu  = s * (1.f/256.f);
                float var = s2 * (1.f/256.f) - mu*mu;
                mu_s[i] = mu;
                rs_s[i] = rsqrtf(var + 1e-5f);
            }
        }
    }
    __syncthreads();
    {
        float g = ln_g[t], be = ln_b[t];
        #pragma unroll
        for (int i = 0; i < 16; i++)
            x_s[i*ISTR + t] = (x_s[i*ISTR + t] - mu_s[i]) * rs_s[i] * g + be;
    }
    __syncthreads();

    // ---- fc1 on concat([x, src]) + relu ----
    ZACC(acc);
    gemv_slabs(fc1_w,       512, 8, x_s,   wbuf, acc, t);
    gemv_slabs(fc1_w + 256, 512, 8, src_s, wbuf, acc, t);
    {
        float4 b1 = *(const float4*)(fc1_b + c0);
        #pragma unroll
        for (int i = 0; i < 4; i++){
            float4 v = make_float4(fmaxf(hadd(acc[0][i]) + b1.x, 0.f),
                                   fmaxf(hadd(acc[1][i]) + b1.y, 0.f),
                                   fmaxf(hadd(acc[2][i]) + b1.z, 0.f),
                                   fmaxf(hadd(acc[3][i]) + b1.w, 0.f));
            *(float4*)(h1_s + (i*4 + bg)*ISTR + c0) = v;
        }
    }
    __syncthreads();

    // ---- fc2 -> z ----
    ZACC(acc);
    gemv_slabs(fc2_w, 256, 8, h1_s, wbuf, acc, t);
    {
        float4 b2 = *(const float4*)(fc2_b + c0);
        #pragma unroll
        for (int i = 0; i < 4; i++){
            float4 v = make_float4(hadd(acc[0][i]) + b2.x,
                                   hadd(acc[1][i]) + b2.y,
                                   hadd(acc[2][i]) + b2.z,
                                   hadd(acc[3][i]) + b2.w);
            *(float4*)(out + (size_t)(b0 + i*4 + bg)*256 + c0) = v;
        }
    }
}

// ---------------------------------------------------------------------------
extern "C" void kernel_launch(void* const* d_in, const int* in_sizes, int n_in,
                              void* d_out, int out_size)
{
    const float* src   = (const float*)d_in[0];
    const float* seq   = (const float*)d_in[1];
    const void*  mask  = d_in[2];
    const float* w_qs  = (const float*)d_in[3];
    const float* w_ks  = (const float*)d_in[4];
    const float* w_vs  = (const float*)d_in[5];
    const float* fc_w  = (const float*)d_in[6];
    const float* fc_b  = (const float*)d_in[7];
    const float* ln_g  = (const float*)d_in[8];
    const float* ln_b  = (const float*)d_in[9];
    const float* fc1_w = (const float*)d_in[10];
    const float* fc1_b = (const float*)d_in[11];
    const float* fc2_w = (const float*)d_in[12];
    const float* fc2_b = (const float*)d_in[13];

    int B = in_sizes[0] / 256;
    if (B > MAXB) B = MAXB;

    float* z = (float*)d_out;
    float* attn_out = nullptr;
    if (out_size >= B*256 + B*512) attn_out = z + (size_t)B*256;

    size_t smem1 = (size_t)(4160 + 4160 + 16384) * sizeof(float);   // ~96.5KB
    size_t smem2 = (size_t)(17040) * sizeof(float);                 // ~66.6KB
    size_t smem3 = (size_t)(49696) * sizeof(float);                 // ~194.1KB
    cudaFuncSetAttribute(k1_qw,   cudaFuncAttributeMaxDynamicSharedMemorySize, (int)smem1);
    cudaFuncSetAttribute(k2_attn, cudaFuncAttributeMaxDynamicSharedMemorySize, (int)smem2);
    cudaFuncSetAttribute(k3_tail, cudaFuncAttributeMaxDynamicSharedMemorySize, (int)smem3);

    k1_qw  <<<B/16, 256, smem1>>>(src, w_qs, w_ks, B);
    k2_attn<<<B,    256, smem2>>>(seq, mask, B, attn_out);
    k3_tail<<<B/16, 256, smem3>>>(src, w_vs, fc_w, fc_b, ln_g, ln_b,
                                  fc1_w, fc1_b, fc2_w, fc2_b, z);
}